// round 11
// baseline (speedup 1.0000x reference)
#include <cuda_runtime.h>
#include <cstdint>

// Problem shape (fixed by setup_inputs): 3 tensors of [B=8, C=256, H=64, W=64] fp32.
#define NB 8
#define NC 256
#define HW 4096              // 64*64
#define K_SEL 2048           // top 50%
#define PER_BATCH (NC * HW)  // 1,048,576 = 2^20 elements
#define PER_TENSOR (NB * PER_BATCH)  // 8,388,608 = 2^23
#define NPOS (3 * NB * HW)   // 98,304 (t,b,hw) positions
#define NTB 24               // 3 * NB
#define NQUAD (NPOS / 4)     // 24,576 float4-position groups
#define HALF4 ((long long)3 * PER_TENSOR / 8)  // 3,145,728 (half of all float4s)

// Scratch (allocation-free rule: __device__ globals)
__device__ float        g_imp[NPOS];           // per-position importance (sum |x| over C)
__device__ unsigned int g_maskbits[NTB * 128]; // 4096-bit mask per (t,b): 12 KB total

// ---------------------------------------------------------------------------
// Kernel 1: importance. Each thread owns 4 adjacent hw positions and walks C
// with ONE float4 load per channel plane. 4 independent accumulators, each a
// strictly-sequential ascending-c chain => per-position result bit-identical
// to the rel_err=0.0 baseline. float4 forces ptxas to keep 8x4 values live
// (unroll 8) => real MLP, unlike the scalar unroll that got recycled (regs=30).
// ---------------------------------------------------------------------------
__global__ void imp_kernel(const float* __restrict__ in0,
                           const float* __restrict__ in1,
                           const float* __restrict__ in2) {
    int q = blockIdx.x * blockDim.x + threadIdx.x;
    if (q >= NQUAD) return;
    int p0 = q << 2;               // first of 4 positions (same (t,b): hw quad never crosses)
    int tb = p0 >> 12;             // t*8 + b
    int hw = p0 & (HW - 1);        // multiple of 4
    int t  = tb >> 3;
    int b  = tb & 7;
    const float* src = (t == 0) ? in0 : (t == 1) ? in1 : in2;
    const float* base = src + ((size_t)b << 20) + hw;

    float s0 = 0.0f, s1 = 0.0f, s2 = 0.0f, s3 = 0.0f;
    #pragma unroll
    for (int c = 0; c < NC; c += 8) {
        float4 v[8];
        #pragma unroll
        for (int j = 0; j < 8; j++)
            v[j] = *reinterpret_cast<const float4*>(base + ((size_t)(c + j) << 12));
        #pragma unroll
        for (int j = 0; j < 8; j++) {
            // each accumulator: sequential, ascending c (no reassociation)
            s0 += fabsf(v[j].x);
            s1 += fabsf(v[j].y);
            s2 += fabsf(v[j].z);
            s3 += fabsf(v[j].w);
        }
    }
    float4 r; r.x = s0; r.y = s1; r.z = s2; r.w = s3;
    *reinterpret_cast<float4*>(&g_imp[p0]) = r;
}

// ---------------------------------------------------------------------------
// Kernel 2: per (t,b) exact k-th-largest via MSB-first radix select on
// composite keys (imp_bits << 12) | (4095 - hw). Keys unique => exactly
// K_SEL selected, top_k lowest-index tie semantics. Warp-aggregated atomics
// (values concentrate in one exponent bucket) + parallel digit scan.
// One block of 512 threads per (t,b); 24 blocks.  [measured-good: ~3us]
// ---------------------------------------------------------------------------
__global__ void select_kernel() {
    __shared__ unsigned long long sk[HW];       // 32 KB
    __shared__ unsigned int hist[256];
    __shared__ unsigned long long s_pref;
    __shared__ unsigned int s_k;

    const int tb   = blockIdx.x;                // 0..23
    const int base = tb * HW;
    const int tid  = threadIdx.x;
    const int bd   = blockDim.x;                // 512
    const int lane = tid & 31;

    for (int i = tid; i < HW; i += bd) {
        // imp >= 0 always -> float bits preserve order as unsigned
        unsigned int fb = __float_as_uint(g_imp[base + i]);
        sk[i] = ((unsigned long long)fb << 12) | (unsigned long long)(HW - 1 - i);
    }
    if (tid == 0) { s_pref = 0ull; s_k = K_SEL; }
    __syncthreads();

    #pragma unroll
    for (int shift = 40; shift >= 0; shift -= 8) {
        if (tid < 256) hist[tid] = 0u;
        __syncthreads();
        const unsigned long long pref = s_pref;
        const unsigned int k = s_k;

        // histogram with warp-aggregated atomics
        for (int i = tid; i < HW; i += bd) {
            unsigned long long key = sk[i];
            bool pred = ((key >> (shift + 8)) == pref);
            unsigned pmask = __ballot_sync(0xffffffffu, pred);
            if (pred) {
                unsigned d = (unsigned)((key >> shift) & 255ull);
                unsigned grp = __match_any_sync(pmask, d);
                if (lane == (__ffs(grp) - 1))
                    atomicAdd(&hist[d], __popc(grp));
            }
        }
        __syncthreads();

        // warp 0: find digit d (from 255 down) where cumulative count reaches k
        if (tid < 32) {
            int base_d = 255 - tid * 8;         // lane covers [base_d-7 .. base_d]
            unsigned sum8 = 0;
            #pragma unroll
            for (int j = 0; j < 8; j++) sum8 += hist[base_d - j];
            unsigned pre = sum8;
            #pragma unroll
            for (int off = 1; off < 32; off <<= 1) {
                unsigned v = __shfl_up_sync(0xffffffffu, pre, off);
                if (tid >= off) pre += v;
            }
            unsigned before = pre - sum8;       // keys in higher digit groups
            if (before < k && k <= pre) {       // exactly one lane
                unsigned rem = k - before;
                for (int d = base_d; ; d--) {
                    unsigned c = hist[d];
                    if (c >= rem) { s_k = rem; s_pref = (pref << 8) | (unsigned)d; break; }
                    rem -= c;
                }
            }
        }
        __syncthreads();
    }

    const unsigned long long thresh = s_pref;   // the K_SEL-th largest key
    for (int i = tid; i < HW; i += bd) {
        bool sel = (sk[i] >= thresh);
        unsigned bal = __ballot_sync(0xffffffffu, sel);
        if (lane == 0) g_maskbits[tb * 128 + (i >> 5)] = bal;
    }
}

// ---------------------------------------------------------------------------
// Kernel 3: out = in * mask. Each thread handles TWO float4s (i, i+HALF4),
// both loads + bitmask words issued before any math (MLP 2x). Bitmask is
// 12 KB, L1/L2-hot. Output: tensor0 | tensor1 | tensor2 concatenated.
// ---------------------------------------------------------------------------
__device__ __forceinline__ void mask_addr(long long i,
                                          const float* in0, const float* in1,
                                          const float* in2,
                                          const float4*& xp, unsigned& midx,
                                          unsigned& shift) {
    long long e = i << 2;
    int t = (int)(e >> 23);
    int r = (int)(e & (PER_TENSOR - 1));
    const float* src = (t == 0) ? in0 : (t == 1) ? in1 : in2;
    int b  = r >> 20;
    int hw = r & (HW - 1);
    xp    = reinterpret_cast<const float4*>(src + r);
    midx  = ((t << 3) + b) * 128 + (hw >> 5);
    shift = hw & 31;
}

__global__ void mask_kernel(const float* __restrict__ in0,
                            const float* __restrict__ in1,
                            const float* __restrict__ in2,
                            float* __restrict__ out) {
    long long i = (long long)blockIdx.x * blockDim.x + threadIdx.x;
    if (i >= HALF4) return;
    long long i2 = i + HALF4;

    const float4 *xp0, *xp1;
    unsigned m0, m1, sh0, sh1;
    mask_addr(i,  in0, in1, in2, xp0, m0, sh0);
    mask_addr(i2, in0, in1, in2, xp1, m1, sh1);

    // issue all loads up front
    float4 x0 = *xp0;
    float4 x1 = *xp1;
    unsigned w0 = __ldg(&g_maskbits[m0]);
    unsigned w1 = __ldg(&g_maskbits[m1]);

    unsigned mb0 = (w0 >> sh0) & 0xFu;
    unsigned mb1 = (w1 >> sh1) & 0xFu;

    float4 y0, y1;
    y0.x = x0.x * ((mb0 & 1u) ? 1.0f : 0.0f);
    y0.y = x0.y * ((mb0 & 2u) ? 1.0f : 0.0f);
    y0.z = x0.z * ((mb0 & 4u) ? 1.0f : 0.0f);
    y0.w = x0.w * ((mb0 & 8u) ? 1.0f : 0.0f);
    y1.x = x1.x * ((mb1 & 1u) ? 1.0f : 0.0f);
    y1.y = x1.y * ((mb1 & 2u) ? 1.0f : 0.0f);
    y1.z = x1.z * ((mb1 & 4u) ? 1.0f : 0.0f);
    y1.w = x1.w * ((mb1 & 8u) ? 1.0f : 0.0f);

    reinterpret_cast<float4*>(out)[i]  = y0;
    reinterpret_cast<float4*>(out)[i2] = y1;
}

// ---------------------------------------------------------------------------
extern "C" void kernel_launch(void* const* d_in, const int* in_sizes, int n_in,
                              void* d_out, int out_size) {
    const float* a = (const float*)d_in[0];
    const float* b = (const float*)d_in[1];
    const float* c = (const float*)d_in[2];
    float* out = (float*)d_out;

    // 1) importance: 24,576 threads, float4 per thread per plane
    imp_kernel<<<(NQUAD + 127) / 128, 128>>>(a, b, c);
    // 2) exact top-k + bitmask build (24 blocks x 512 threads)
    select_kernel<<<NTB, 512>>>();
    // 3) masked write: 2 float4 per thread
    mask_kernel<<<(unsigned)((HALF4 + 255) / 256), 256>>>(a, b, c, out);
}